// round 1
// baseline (speedup 1.0000x reference)
#include <cuda_runtime.h>
#include <cuda_bf16.h>
#include <cstdint>

// Problem shape (fixed by the dataset):
//   masks    : [B=16, T=512, F=1024, C=4]  float32   -> 2^25 elements
//   src_stft : [B=16, T=512, 2F=2048, C=4] float32
// loss = mean_{b,t,f,c} | masks[b,t,f,c] - onehot(argmax_c src_stft[b,t,f,c]) |
//
// Group view: each (b,t,f) is one float4 in masks and one float4 in the first
// half of src_stft's dim-2. NG = 16*512*1024 = 8,388,608 groups.

static constexpr int NG        = 16 * 512 * 1024;   // float4 groups
static constexpr float INV_N   = 1.0f / 33554432.0f; // 1 / 2^25 (exact)

__global__ void zero_out_kernel(float* out) {
    out[0] = 0.0f;
}

__global__ __launch_bounds__(256) void recon_loss_kernel(
    const float4* __restrict__ masks,
    const float4* __restrict__ stft,
    float* __restrict__ out)
{
    float acc = 0.0f;
    const int stride = gridDim.x * blockDim.x;
    int i = blockIdx.x * blockDim.x + threadIdx.x;

    #pragma unroll 4
    for (; i < NG; i += stride) {
        // i = bt * 1024 + f ;  gt group index = bt * 2048 + f
        const int bt = i >> 10;
        const int f  = i & 1023;
        const float4 g = __ldg(&stft[(bt << 11) + f]);
        const float4 m = __ldg(&masks[i]);

        // first-max argmax over 4 channels (strict > keeps earliest index)
        int j = 0;
        float best = g.x;
        if (g.y > best) { best = g.y; j = 1; }
        if (g.z > best) { best = g.z; j = 2; }
        if (g.w > best) { best = g.w; j = 3; }

        acc += fabsf(m.x - (j == 0 ? 1.0f : 0.0f));
        acc += fabsf(m.y - (j == 1 ? 1.0f : 0.0f));
        acc += fabsf(m.z - (j == 2 ? 1.0f : 0.0f));
        acc += fabsf(m.w - (j == 3 ? 1.0f : 0.0f));
    }

    // warp reduce
    #pragma unroll
    for (int off = 16; off > 0; off >>= 1)
        acc += __shfl_xor_sync(0xFFFFFFFFu, acc, off);

    __shared__ float warp_sums[8];
    const int lane = threadIdx.x & 31;
    const int wid  = threadIdx.x >> 5;
    if (lane == 0) warp_sums[wid] = acc;
    __syncthreads();

    if (wid == 0) {
        float s = (lane < 8) ? warp_sums[lane] : 0.0f;
        #pragma unroll
        for (int off = 4; off > 0; off >>= 1)
            s += __shfl_xor_sync(0xFFFFFFFFu, s, off);
        if (lane == 0)
            atomicAdd(out, s * INV_N);
    }
}

extern "C" void kernel_launch(void* const* d_in, const int* in_sizes, int n_in,
                              void* d_out, int out_size)
{
    const float4* masks = (const float4*)d_in[0];
    const float4* stft  = (const float4*)d_in[1];
    float* out = (float*)d_out;

    zero_out_kernel<<<1, 1>>>(out);

    // 148 SMs; 16 blocks/SM of 256 threads -> 2368 blocks, ~28 iters/thread.
    const int blocks  = 148 * 16;
    const int threads = 256;
    recon_loss_kernel<<<blocks, threads>>>(masks, stft, out);
}

// round 4
// speedup vs baseline: 1.0617x; 1.0617x over previous
#include <cuda_runtime.h>
#include <cuda_bf16.h>
#include <cstdint>

// Shape: masks [16,512,1024,4] f32, src_stft [16,512,2048,4] f32.
// loss = mean |masks - onehot(argmax_C src_stft[:,:,:1024,:])|
// Group view: NG = 2^23 float4 pairs.

static constexpr int   NG      = 16 * 512 * 1024;      // 8,388,608 groups
static constexpr int   THREADS = 256;
static constexpr int   BLOCKS  = 2048;
static constexpr int   STRIDE  = THREADS * BLOCKS;     // 524,288
static constexpr int   U       = 4;
static constexpr int   OUTER   = NG / (STRIDE * U);    // 4, exact
static constexpr float INV_N   = 1.0f / 33554432.0f;   // 1 / 2^25 (exact)

__device__ float        g_partial; // zero-init at load; reset by last block each run
__device__ unsigned int g_count;

__global__ __launch_bounds__(THREADS) void recon_loss_kernel(
    const float4* __restrict__ masks,
    const float4* __restrict__ stft,
    float* __restrict__ out)
{
    const int tid = blockIdx.x * THREADS + threadIdx.x;
    float acc = 0.0f;

    #pragma unroll 1
    for (int outer = 0; outer < OUTER; outer++) {
        float4 m[U], g[U];
        // Front-batched independent 128-bit loads: MLP = 2*U = 8 per body.
        #pragma unroll
        for (int u = 0; u < U; u++) {
            const int i  = tid + (outer * U + u) * STRIDE;
            const int bt = i >> 10;
            const int f  = i & 1023;
            g[u] = __ldcs(&stft[(bt << 11) + f]);   // single-use: evict-first
            m[u] = __ldcs(&masks[i]);
        }
        #pragma unroll
        for (int u = 0; u < U; u++) {
            // first-max argmax over C=4 (strict > keeps earliest index)
            int j = 0;
            float best = g[u].x;
            if (g[u].y > best) { best = g[u].y; j = 1; }
            if (g[u].z > best) { best = g[u].z; j = 2; }
            if (g[u].w > best) { best = g[u].w; j = 3; }
            acc += fabsf(m[u].x - (j == 0 ? 1.0f : 0.0f));
            acc += fabsf(m[u].y - (j == 1 ? 1.0f : 0.0f));
            acc += fabsf(m[u].z - (j == 2 ? 1.0f : 0.0f));
            acc += fabsf(m[u].w - (j == 3 ? 1.0f : 0.0f));
        }
    }

    // warp reduce
    #pragma unroll
    for (int off = 16; off > 0; off >>= 1)
        acc += __shfl_xor_sync(0xFFFFFFFFu, acc, off);

    __shared__ float warp_sums[THREADS / 32];
    const int lane = threadIdx.x & 31;
    const int wid  = threadIdx.x >> 5;
    if (lane == 0) warp_sums[wid] = acc;
    __syncthreads();

    if (wid == 0) {
        float s = (lane < THREADS / 32) ? warp_sums[lane] : 0.0f;
        #pragma unroll
        for (int off = 4; off > 0; off >>= 1)
            s += __shfl_xor_sync(0xFFFFFFFFu, s, off);

        if (lane == 0) {
            atomicAdd(&g_partial, s);
            __threadfence();
            const unsigned done = atomicAdd(&g_count, 1u);
            if (done == (unsigned)gridDim.x - 1u) {
                // Last block: read-and-reset atomically so graph replays are
                // deterministic (g_partial/g_count return to 0 every call).
                const float total = atomicExch(&g_partial, 0.0f);
                atomicExch(&g_count, 0u);
                out[0] = total * INV_N;
            }
        }
    }
}

extern "C" void kernel_launch(void* const* d_in, const int* in_sizes, int n_in,
                              void* d_out, int out_size)
{
    const float4* masks = (const float4*)d_in[0];
    const float4* stft  = (const float4*)d_in[1];
    float* out = (float*)d_out;

    recon_loss_kernel<<<BLOCKS, THREADS>>>(masks, stft, out);
}